// round 15
// baseline (speedup 1.0000x reference)
#include <cuda_runtime.h>
#include <math.h>

#define NGT 32
#define NKEY (49152 + 12288 + 3072)
#define NBIN 4096

// Static scratch (no cudaMalloc anywhere). Zero-initialized at load; every
// kernel restores its state to zero each call (graph-replay safe).
__device__ unsigned g_negkey[64 * NKEY];
__device__ unsigned g_cand[64 * NKEY];     // threshold-bin candidates
__device__ unsigned g_hist[192 * NBIN];    // fused 12-bit histogram
__device__ unsigned g_subhist[192 * NBIN]; // second-level 12-bit histogram
__device__ int      g_numpos[192];
__device__ int      g_bin[192];
__device__ int      g_kr[192];
__device__ unsigned g_nc[192];
__device__ float    g_psum[192];
__device__ unsigned g_hdone[192];
__device__ unsigned g_sdone[192];
__device__ float    g_total;
__device__ unsigned g_done;

__device__ __forceinline__ float sl1(float x) {
    float ax = fabsf(x);
    return ax < 1.0f ? 0.5f * x * x : ax - 0.5f;
}

// Block-parallel suffix select over nbins (256 or 4096) counters: largest v
// with suffix-count >= k; fallback to v=0 when total < k (kr adjusted as if
// bin 0 absorbs the shortfall — bin 0 only ever holds zero-valued sentinel
// keys, whose sign bit is clear, so ties at a zero threshold are skipped).
// First 256 threads participate; ALL block threads must call (internal syncs).
__device__ void selectHi(const unsigned* h, int nbins, int k,
                         int* out_v, int* out_kr, int tid)
{
    __shared__ int wsuf[8];
    __shared__ int s_tot;
    int lane = tid & 31, w = tid >> 5;
    int seg = 0, incl = 0;
    int BPT = nbins >> 8;
    if (tid < 256) {
        int base = tid * BPT;
        for (int i = 0; i < BPT; i++) seg += (int)h[base + i];
        incl = seg;
        #pragma unroll
        for (int off = 1; off < 32; off <<= 1) {
            int u = __shfl_down_sync(0xffffffffu, incl, off);
            if (lane + off < 32) incl += u;
        }
        if (lane == 0) wsuf[w] = incl;   // warp totals (temporarily)
    }
    __syncthreads();
    if (tid < 32) {
        int t = (tid < 8) ? wsuf[tid] : 0;
        int inc = t;
        #pragma unroll
        for (int off = 1; off < 8; off <<= 1) {
            int u = __shfl_down_sync(0xffffffffu, inc, off);
            if (tid + off < 8) inc += u;
        }
        if (tid < 8) wsuf[tid] = inc - t;   // suffix-exclusive across warps
        if (tid == 0) s_tot = inc;          // grand total (warp 0 inclusive)
    }
    __syncthreads();
    if (tid < 256) {
        int sufExcl = wsuf[w] + (incl - seg);
        int sufIncl = sufExcl + seg;
        if (sufExcl < k && sufIncl >= k) {  // exactly one owner thread
            int cum = sufExcl;
            int base = tid * BPT;
            for (int i = BPT - 1; i >= 0; i--) {
                int c = (int)h[base + i];
                if (cum + c >= k) { *out_v = base + i; *out_kr = k - cum; break; }
                cum += c;
            }
        }
        if (tid == 0 && s_tot < k) {
            *out_v = 0; *out_kr = k - (s_tot - (int)h[0]);
        }
    }
    __syncthreads();
}

// Fused matcher: ALL scales in one launch. blockIdx.x in [0,84):
//   [0,64)  scale 0: W=128, stride 8,  tiles 4x16 of 32x8 positions
//   [64,80) scale 1: W=64,  stride 16
//   [80,84) scale 2: W=32,  stride 32
// Thread = 1 position x 3 anchor sizes. GT pruning, closed-form anchors,
// division-free argmax (all bit-exact vs reference semantics). The last
// tile-block per (b,s) selects the 12-bit threshold bin in-kernel.
__global__ __launch_bounds__(256) void k_all(
    const float* __restrict__ p0, const float* __restrict__ p1,
    const float* __restrict__ p2, const float* __restrict__ gtb,
    const int* __restrict__ gtl)
{
    __shared__ float sgx1[NGT], sgy1[NGT], sgx2[NGT], sgy2[NGT], sgar[NGT];
    __shared__ int slab[NGT];
    __shared__ int sK;
    __shared__ unsigned hist[NBIN];
    __shared__ float rs[8];
    __shared__ int rp[8];
    __shared__ int s_last, s_np, s_v, s_kr;

    int bsx = blockIdx.x;
    int b = blockIdx.y;
    const float* pred;
    int W, tilesX, sIdx, tile, tcnt;
    float stride;
    size_t segoff;
    if (bsx < 64)      { pred = p0; W = 128; tilesX = 4; stride = 8.f;  sIdx = 0; segoff = 0;                            tile = bsx;      tcnt = 64; }
    else if (bsx < 80) { pred = p1; W = 64;  tilesX = 2; stride = 16.f; sIdx = 1; segoff = (size_t)64 * 49152;           tile = bsx - 64; tcnt = 16; }
    else               { pred = p2; W = 32;  tilesX = 1; stride = 32.f; sIdx = 2; segoff = (size_t)64 * (49152 + 12288); tile = bsx - 80; tcnt = 4;  }
    int bs = sIdx * 64 + b;

    int ti = tile / tilesX;
    int tj = tile - ti * tilesX;
    int tid = threadIdx.x;
    int tx = tid & 31, ty = tid >> 5;
    int j = tj * 32 + tx;
    int i = ti * 8 + ty;
    int HW = W * W;

    for (int z = tid; z < NBIN; z += 256) hist[z] = 0;

    // GT candidate compaction (warp 0). Tile bbox covers the largest anchor
    // half-extent (2.5*stride). Strict inequality: touching => IoU 0.
    if (tid < 32) {
        float xlo = (tj * 32 + 0.5f) * stride - 2.5f * stride;
        float xhi = (tj * 32 + 31.5f) * stride + 2.5f * stride;
        float ylo = (ti * 8 + 0.5f) * stride - 2.5f * stride;
        float yhi = (ti * 8 + 7.5f) * stride + 2.5f * stride;
        const float* g = gtb + ((size_t)b * NGT + tid) * 4;
        float gx1 = g[0], gy1 = g[1], gx2 = g[2], gy2 = g[3];
        bool ov = (gx1 < xhi) && (gx2 > xlo) && (gy1 < yhi) && (gy2 > ylo);
        unsigned m = __ballot_sync(0xffffffffu, ov);
        if (ov) {
            int p = __popc(m & ((1u << tid) - 1u));
            sgx1[p] = gx1; sgy1[p] = gy1; sgx2[p] = gx2; sgy2[p] = gy2;
            sgar[p] = (gx2 - gx1) * (gy2 - gy1);
            slab[p] = gtl[b * NGT + tid];
        }
        if (tid == 0) sK = __popc(m);
    }
    __syncthreads();
    int K = sK;

    float cpx = (j + 0.5f) * stride;
    float cpy = (i + 0.5f) * stride;
    float halfv[3] = {1.5f * stride, 2.0f * stride, 2.5f * stride};
    float ax1[3], ay1[3], ax2[3], ay2[3], areaA[3];
    #pragma unroll
    for (int a = 0; a < 3; a++) {
        ax1[a] = cpx - halfv[a]; ax2[a] = cpx + halfv[a];
        ay1[a] = cpy - halfv[a]; ay2[a] = cpy + halfv[a];
        float s2 = 2.0f * halfv[a];
        areaA[a] = s2 * s2;
    }

    // Division-free argmax; init (0, 1, idx 0) preserves argmax-first
    // semantics when all IoUs are 0.
    float bi[3] = {0.f, 0.f, 0.f}, bd[3] = {1.f, 1.f, 1.f};
    int bx[3] = {0, 0, 0};
    for (int kk = 0; kk < K; kk++) {
        float g1 = sgx1[kk], g2 = sgy1[kk], g3 = sgx2[kk], g4 = sgy2[kk];
        float ga = sgar[kk];
        #pragma unroll
        for (int a = 0; a < 3; a++) {
            float lx = fmaxf(ax1[a], g1);
            float ly = fmaxf(ay1[a], g2);
            float rx = fminf(ax2[a], g3);
            float ry = fminf(ay2[a], g4);
            float w = fmaxf(rx - lx, 0.f);
            float h = fmaxf(ry - ly, 0.f);
            float in = w * h;
            float d = areaA[a] + ga - in + 1e-9f;
            if (in * bd[a] > bi[a] * d) { bi[a] = in; bd[a] = d; bx[a] = kk; }
        }
    }

    float acc = 0.f;
    int posc = 0;
    int hw = i * W + j;
    const float* pbb = pred + (size_t)b * 24 * HW + hw;

    #pragma unroll
    for (int a = 0; a < 3; a++) {
        float best = bi[a] / bd[a];   // one exact IEEE division per anchor
        bool pos = best >= 0.5f;
        bool neg = best < 0.4f;
        const float* pb = pbb + (size_t)(a * 8) * HW;
        float p4 = pb[(size_t)4 * HW];
        float obj = fmaxf(p4, 0.f) - (pos ? p4 : 0.f)
                  + __logf(1.0f + __expf(-fabsf(p4)));

        if (pos) {
            posc++;
            float q0 = pb[0];
            float q1 = pb[(size_t)HW];
            float q2 = pb[(size_t)2 * HW];
            float q3 = pb[(size_t)3 * HW];
            float q5 = pb[(size_t)5 * HW];
            float q6 = pb[(size_t)6 * HW];
            float q7 = pb[(size_t)7 * HW];
            int m = bx[a];
            float m0 = sgx1[m], m1 = sgy1[m], m2 = sgx2[m], m3 = sgy2[m];
            float ax = (ax1[a] + ax2[a]) * 0.5f;
            float ay = (ay1[a] + ay2[a]) * 0.5f;
            float aw = fmaxf(ax2[a] - ax1[a], 1e-6f);
            float ah = fmaxf(ay2[a] - ay1[a], 1e-6f);
            float gx = (m0 + m2) * 0.5f;
            float gy = (m1 + m3) * 0.5f;
            float gw = fmaxf(m2 - m0, 1e-6f);
            float gh = fmaxf(m3 - m1, 1e-6f);
            float loc = sl1(q0 - (gx - ax) / aw) + sl1(q1 - (gy - ay) / ah)
                      + sl1(q2 - __logf(gw / aw)) + sl1(q3 - __logf(gh / ah));
            float mx = fmaxf(q5, fmaxf(q6, q7));
            float lse = mx + __logf(__expf(q5 - mx) + __expf(q6 - mx) + __expf(q7 - mx));
            int tgt = slab[m]; if (tgt < 0) tgt = 0;
            float pt = (tgt == 0) ? q5 : ((tgt == 1) ? q6 : q7);
            acc += loc + obj + (lse - pt);
        }

        unsigned key = neg ? (__float_as_uint(obj) | 0x80000000u) : 0u;
        g_negkey[segoff + (size_t)b * (3 * HW) + (size_t)a * HW + hw] = key;

        // fused radix pass: 12-bit histogram (warp-aggregated)
        unsigned bkt = key >> 20;
        unsigned mm = __match_any_sync(0xffffffffu, bkt);
        if ((tid & 31) == __ffs(mm) - 1)
            atomicAdd(&hist[bkt], (unsigned)__popc(mm));
    }

    // Block reduce loss partial + positive count.
    float v = acc; int pc = posc;
    #pragma unroll
    for (int o = 16; o; o >>= 1) {
        v  += __shfl_down_sync(0xffffffffu, v, o);
        pc += __shfl_down_sync(0xffffffffu, pc, o);
    }
    if ((tid & 31) == 0) { rs[tid >> 5] = v; rp[tid >> 5] = pc; }
    __syncthreads();

    // Flush histogram (skip zero bins).
    for (int z = tid; z < NBIN; z += 256) {
        unsigned c = hist[z];
        if (c) atomicAdd(&g_hist[bs * NBIN + z], c);
    }

    if (tid < 32) {
        v  = (tid < 8) ? rs[tid] : 0.f;
        pc = (tid < 8) ? rp[tid] : 0;
        #pragma unroll
        for (int o = 4; o; o >>= 1) {
            v  += __shfl_down_sync(0xffffffffu, v, o);
            pc += __shfl_down_sync(0xffffffffu, pc, o);
        }
        if (tid == 0) {
            if (v != 0.f) atomicAdd(&g_total, v);
            if (pc)       atomicAdd(&g_numpos[bs], pc);
        }
    }

    // Last tile-block per (b,s): select threshold bin from the full histogram.
    __threadfence();
    __syncthreads();
    if (tid == 0) {
        unsigned d = atomicAdd(&g_hdone[bs], 1u);
        s_last = (d == (unsigned)(tcnt - 1));
    }
    __syncthreads();
    if (s_last) {
        __threadfence();   // acquire: see all other blocks' flushes
        if (tid == 0) {
            g_hdone[bs] = 0;
            s_np = atomicExch(&g_numpos[bs], 0);
        }
        for (int z = tid; z < NBIN; z += 256) {
            hist[z] = g_hist[bs * NBIN + z];
            g_hist[bs * NBIN + z] = 0;
        }
        __syncthreads();
        int np = s_np;
        int k = 3 * (np > 1 ? np : 1);
        selectHi(hist, NBIN, k, &s_v, &s_kr, tid);
        if (tid == 0) { g_bin[bs] = s_v; g_kr[bs] = s_kr; }
    }
}

// Balanced key scan: 11 chunk-blocks per image (8 for s0, 2 for s1, 1 for s2).
// Each block sums keys above the threshold bin, compacts bin members, and
// histograms their middle 12 bits. The last chunk-block per (b,s) resolves the
// remaining 20 bits over the candidates; the globally-last block finalizes.
__global__ __launch_bounds__(512) void k_scan(float* __restrict__ out)
{
    __shared__ unsigned sh[NBIN];
    __shared__ unsigned cnt8[256];
    __shared__ float fsb[256];
    __shared__ float red[16];
    __shared__ int s_last, s_v, s_kr, s_nc;
    __shared__ float s_pa;

    int cx = blockIdx.x, b = blockIdx.y;
    int s, chunk, nchunks, N;
    size_t off;
    if (cx < 8)       { s = 0; chunk = cx;     nchunks = 8; N = 49152; off = 0; }
    else if (cx < 10) { s = 1; chunk = cx - 8; nchunks = 2; N = 12288; off = (size_t)64 * 49152; }
    else              { s = 2; chunk = 0;      nchunks = 1; N = 3072;  off = (size_t)64 * (49152 + 12288); }
    int bs = s * 64 + b;
    int chunkN = N / nchunks;

    int tid = threadIdx.x;
    int lane = tid & 31;
    unsigned* cand = g_cand + off + (size_t)b * N;

    int v = g_bin[bs];
    int kr = g_kr[bs];

    const uint4* k4 = (const uint4*)(g_negkey + off + (size_t)b * N
                                     + (size_t)chunk * chunkN);
    float lsum = 0.f;
    for (int idx = tid; idx < (chunkN >> 2); idx += 512) {
        uint4 q = __ldg(k4 + idx);
        unsigned kk[4] = {q.x, q.y, q.z, q.w};
        #pragma unroll
        for (int e = 0; e < 4; e++) {
            unsigned key = kk[e];
            int bin = (int)(key >> 20);
            if (bin > v) lsum += __uint_as_float(key & 0x7fffffffu);
            else if (bin == v) {
                unsigned am = __activemask();
                int leader = __ffs(am) - 1;
                int base;
                if (lane == leader) base = (int)atomicAdd(&g_nc[bs], (unsigned)__popc(am));
                base = __shfl_sync(am, base, leader);
                base += __popc(am & ((1u << lane) - 1u));
                cand[base] = key;
                atomicAdd(&g_subhist[bs * NBIN + ((key >> 8) & 4095u)], 1u);
            }
        }
    }
    // block reduce above-sum -> per-(b,s) partial
    #pragma unroll
    for (int o = 16; o; o >>= 1) lsum += __shfl_down_sync(0xffffffffu, lsum, o);
    if (lane == 0) red[tid >> 5] = lsum;
    __syncthreads();
    if (tid < 16) {
        float x = red[tid];
        #pragma unroll
        for (int o = 8; o; o >>= 1) x += __shfl_down_sync(0xffffu, x, o);
        if (tid == 0 && x != 0.f) atomicAdd(&g_psum[bs], x);
    }

    __threadfence();
    __syncthreads();
    if (tid == 0) {
        unsigned d = atomicAdd(&g_sdone[bs], 1u);
        s_last = (d == (unsigned)(nchunks - 1));
    }
    __syncthreads();
    if (!s_last) return;

    // ---- resolution (one block per (b,s)) ----
    __threadfence();   // acquire: see all chunk blocks' cand/subhist/psum
    if (tid == 0) {
        g_sdone[bs] = 0;
        s_nc = (int)atomicExch(&g_nc[bs], 0u);
        s_pa = atomicExch(&g_psum[bs], 0.f);
    }
    for (int z = tid; z < NBIN; z += 512) {
        sh[z] = g_subhist[bs * NBIN + z];
        g_subhist[bs * NBIN + z] = 0;
    }
    __syncthreads();
    int nc = s_nc;

    selectHi(sh, NBIN, kr, &s_v, &s_kr, tid);
    int v2 = s_v;
    int kr2 = s_kr;
    if (tid < 256) { cnt8[tid] = 0; fsb[tid] = 0.f; }
    __syncthreads();

    float lsum2 = 0.f;
    for (int z = tid; z < nc; z += 512) {
        unsigned key = cand[z];
        int mid = (int)((key >> 8) & 4095u);
        if (mid > v2) lsum2 += __uint_as_float(key & 0x7fffffffu);
        else if (mid == v2) {
            unsigned bkt = key & 255u;
            atomicAdd(&cnt8[bkt], 1u);
            atomicAdd(&fsb[bkt], __uint_as_float(key & 0x7fffffffu));
        }
    }
    __syncthreads();
    selectHi(cnt8, 256, kr2, &s_v, &s_kr, tid);
    int v0 = s_v;
    int krF = s_kr;
    unsigned T = ((unsigned)v << 20) | ((unsigned)v2 << 8) | (unsigned)v0;

    if (tid < 256 && tid > v0) lsum2 += fsb[tid];

    #pragma unroll
    for (int o = 16; o; o >>= 1) lsum2 += __shfl_down_sync(0xffffffffu, lsum2, o);
    if (lane == 0) red[tid >> 5] = lsum2;
    __syncthreads();
    if (tid < 16) {
        float x = red[tid];
        #pragma unroll
        for (int o = 8; o; o >>= 1) x += __shfl_down_sync(0xffffu, x, o);
        if (tid == 0) {
            x += s_pa;
            if (T & 0x80000000u)   // real threshold -> ties contribute
                x += (float)krF * __uint_as_float(T & 0x7fffffffu);
            if (x != 0.f) atomicAdd(&g_total, x);

            // globally-last finalizer
            __threadfence();
            unsigned done = atomicAdd(&g_done, 1u);
            if (done == 191u) {
                float tot = atomicAdd(&g_total, 0.0f);  // ordered read
                out[0] = tot * (1.0f / 64.0f);
                g_total = 0.0f;
                g_done = 0u;
            }
        }
    }
}

extern "C" void kernel_launch(void* const* d_in, const int* in_sizes, int n_in,
                              void* d_out, int out_size)
{
    const float *pred0 = 0, *pred1 = 0, *pred2 = 0, *gtb = 0;
    const int *gtl = 0;
    for (int i = 0; i < n_in; ++i) {
        switch (in_sizes[i]) {
            case 25165824: pred0 = (const float*)d_in[i]; break; // 64*24*128*128
            case 6291456:  pred1 = (const float*)d_in[i]; break; // 64*24*64*64
            case 1572864:  pred2 = (const float*)d_in[i]; break; // 64*24*32*32
            case 8192:     gtb   = (const float*)d_in[i]; break; // 64*32*4
            case 2048:     gtl   = (const int*)d_in[i];   break; // 64*32
        }
    }

    k_all<<<dim3(84, 64), 256>>>(pred0, pred1, pred2, gtb, gtl);
    k_scan<<<dim3(11, 64), 512>>>((float*)d_out);
}

// round 17
// speedup vs baseline: 1.2455x; 1.2455x over previous
#include <cuda_runtime.h>
#include <math.h>

#define NGT 32
#define NKEY (49152 + 12288 + 3072)
#define NBIN 4096

// Static scratch (no cudaMalloc anywhere). Zero-initialized at load; every
// kernel restores its state to zero each call (graph-replay safe).
__device__ unsigned g_negkey[64 * NKEY];
__device__ unsigned g_cand[64 * NKEY];   // threshold-bucket candidates
__device__ int      g_numpos[192];
__device__ float    g_total;
__device__ unsigned g_done;

__device__ __forceinline__ float sl1(float x) {
    float ax = fabsf(x);
    return ax < 1.0f ? 0.5f * x * x : ax - 0.5f;
}

// Fused matcher: ALL scales in one launch. blockIdx.x in [0,84):
//   [0,64)  scale 0: W=128, stride 8,  tiles 4x16 of 32x8 positions
//   [64,80) scale 1: W=64,  stride 16
//   [80,84) scale 2: W=32,  stride 32
// Thread = 1 position x 3 anchor sizes. GT pruning, closed-form anchors,
// division-free argmax (bit-exact vs reference semantics).
__global__ __launch_bounds__(256) void k_all(
    const float* __restrict__ p0, const float* __restrict__ p1,
    const float* __restrict__ p2, const float* __restrict__ gtb,
    const int* __restrict__ gtl)
{
    __shared__ float sgx1[NGT], sgy1[NGT], sgx2[NGT], sgy2[NGT], sgar[NGT];
    __shared__ int slab[NGT];
    __shared__ int sK;
    __shared__ float rs[8];
    __shared__ int rp[8];

    int bsx = blockIdx.x;
    int b = blockIdx.y;
    const float* pred;
    int W, tilesX, sIdx, tile;
    float stride;
    size_t segoff;
    if (bsx < 64)      { pred = p0; W = 128; tilesX = 4; stride = 8.f;  sIdx = 0; segoff = 0;                            tile = bsx; }
    else if (bsx < 80) { pred = p1; W = 64;  tilesX = 2; stride = 16.f; sIdx = 1; segoff = (size_t)64 * 49152;           tile = bsx - 64; }
    else               { pred = p2; W = 32;  tilesX = 1; stride = 32.f; sIdx = 2; segoff = (size_t)64 * (49152 + 12288); tile = bsx - 80; }

    int ti = tile / tilesX;
    int tj = tile - ti * tilesX;
    int tid = threadIdx.x;
    int tx = tid & 31, ty = tid >> 5;
    int j = tj * 32 + tx;
    int i = ti * 8 + ty;
    int HW = W * W;

    // GT candidate compaction (warp 0). Tile bbox covers the largest anchor
    // half-extent (2.5*stride). Strict inequality: touching => IoU 0.
    if (tid < 32) {
        float xlo = (tj * 32 + 0.5f) * stride - 2.5f * stride;
        float xhi = (tj * 32 + 31.5f) * stride + 2.5f * stride;
        float ylo = (ti * 8 + 0.5f) * stride - 2.5f * stride;
        float yhi = (ti * 8 + 7.5f) * stride + 2.5f * stride;
        const float* g = gtb + ((size_t)b * NGT + tid) * 4;
        float gx1 = g[0], gy1 = g[1], gx2 = g[2], gy2 = g[3];
        bool ov = (gx1 < xhi) && (gx2 > xlo) && (gy1 < yhi) && (gy2 > ylo);
        unsigned m = __ballot_sync(0xffffffffu, ov);
        if (ov) {
            int p = __popc(m & ((1u << tid) - 1u));
            sgx1[p] = gx1; sgy1[p] = gy1; sgx2[p] = gx2; sgy2[p] = gy2;
            sgar[p] = (gx2 - gx1) * (gy2 - gy1);
            slab[p] = gtl[b * NGT + tid];
        }
        if (tid == 0) sK = __popc(m);
    }
    __syncthreads();
    int K = sK;

    float cpx = (j + 0.5f) * stride;
    float cpy = (i + 0.5f) * stride;
    float halfv[3] = {1.5f * stride, 2.0f * stride, 2.5f * stride};
    float ax1[3], ay1[3], ax2[3], ay2[3], areaA[3];
    #pragma unroll
    for (int a = 0; a < 3; a++) {
        ax1[a] = cpx - halfv[a]; ax2[a] = cpx + halfv[a];
        ay1[a] = cpy - halfv[a]; ay2[a] = cpy + halfv[a];
        float s2 = 2.0f * halfv[a];
        areaA[a] = s2 * s2;
    }

    // Division-free argmax; init (0, 1, idx 0) preserves argmax-first
    // semantics when all IoUs are 0.
    float bi[3] = {0.f, 0.f, 0.f}, bd[3] = {1.f, 1.f, 1.f};
    int bx[3] = {0, 0, 0};
    for (int kk = 0; kk < K; kk++) {
        float g1 = sgx1[kk], g2 = sgy1[kk], g3 = sgx2[kk], g4 = sgy2[kk];
        float ga = sgar[kk];
        #pragma unroll
        for (int a = 0; a < 3; a++) {
            float lx = fmaxf(ax1[a], g1);
            float ly = fmaxf(ay1[a], g2);
            float rx = fminf(ax2[a], g3);
            float ry = fminf(ay2[a], g4);
            float w = fmaxf(rx - lx, 0.f);
            float h = fmaxf(ry - ly, 0.f);
            float in = w * h;
            float d = areaA[a] + ga - in + 1e-9f;
            if (in * bd[a] > bi[a] * d) { bi[a] = in; bd[a] = d; bx[a] = kk; }
        }
    }

    float acc = 0.f;
    int posc = 0;
    int hw = i * W + j;
    const float* pbb = pred + (size_t)b * 24 * HW + hw;

    #pragma unroll
    for (int a = 0; a < 3; a++) {
        float best = bi[a] / bd[a];   // one exact IEEE division per anchor
        bool pos = best >= 0.5f;
        bool neg = best < 0.4f;
        const float* pb = pbb + (size_t)(a * 8) * HW;
        float p4 = pb[(size_t)4 * HW];
        float obj = fmaxf(p4, 0.f) - (pos ? p4 : 0.f)
                  + __logf(1.0f + __expf(-fabsf(p4)));

        if (pos) {
            posc++;
            float q0 = pb[0];
            float q1 = pb[(size_t)HW];
            float q2 = pb[(size_t)2 * HW];
            float q3 = pb[(size_t)3 * HW];
            float q5 = pb[(size_t)5 * HW];
            float q6 = pb[(size_t)6 * HW];
            float q7 = pb[(size_t)7 * HW];
            int m = bx[a];
            float m0 = sgx1[m], m1 = sgy1[m], m2 = sgx2[m], m3 = sgy2[m];
            float ax = (ax1[a] + ax2[a]) * 0.5f;
            float ay = (ay1[a] + ay2[a]) * 0.5f;
            float aw = fmaxf(ax2[a] - ax1[a], 1e-6f);
            float ah = fmaxf(ay2[a] - ay1[a], 1e-6f);
            float gx = (m0 + m2) * 0.5f;
            float gy = (m1 + m3) * 0.5f;
            float gw = fmaxf(m2 - m0, 1e-6f);
            float gh = fmaxf(m3 - m1, 1e-6f);
            float loc = sl1(q0 - (gx - ax) / aw) + sl1(q1 - (gy - ay) / ah)
                      + sl1(q2 - __logf(gw / aw)) + sl1(q3 - __logf(gh / ah));
            float mx = fmaxf(q5, fmaxf(q6, q7));
            float lse = mx + __logf(__expf(q5 - mx) + __expf(q6 - mx) + __expf(q7 - mx));
            int tgt = slab[m]; if (tgt < 0) tgt = 0;
            float pt = (tgt == 0) ? q5 : ((tgt == 1) ? q6 : q7);
            acc += loc + obj + (lse - pt);
        }

        unsigned key = neg ? (__float_as_uint(obj) | 0x80000000u) : 0u;
        g_negkey[segoff + (size_t)b * (3 * HW) + (size_t)a * HW + hw] = key;
    }

    // Block reduce loss partial + positive count.
    float v = acc; int pc = posc;
    #pragma unroll
    for (int o = 16; o; o >>= 1) {
        v  += __shfl_down_sync(0xffffffffu, v, o);
        pc += __shfl_down_sync(0xffffffffu, pc, o);
    }
    if ((tid & 31) == 0) { rs[tid >> 5] = v; rp[tid >> 5] = pc; }
    __syncthreads();
    if (tid < 32) {
        v  = (tid < 8) ? rs[tid] : 0.f;
        pc = (tid < 8) ? rp[tid] : 0;
        #pragma unroll
        for (int o = 4; o; o >>= 1) {
            v  += __shfl_down_sync(0xffffffffu, v, o);
            pc += __shfl_down_sync(0xffffffffu, pc, o);
        }
        if (tid == 0) {
            if (v != 0.f) atomicAdd(&g_total, v);
            if (pc)       atomicAdd(&g_numpos[sIdx * 64 + b], pc);
        }
    }
}

// Block-parallel suffix select over nbins (256/4096) counters: largest v with
// suffix-count >= k; fallback to v=0 when total < k (kr adjusted as if bin 0
// absorbs the shortfall — bin 0 only holds zero-valued sentinel keys, whose
// sign bit is clear, so ties at a zero threshold are skipped by the caller).
// First 256 threads participate; ALL block threads must call (internal syncs).
__device__ void selectHi(const unsigned* h, int nbins, int k,
                         int* out_v, int* out_kr, int tid)
{
    __shared__ int wsuf[8];
    __shared__ int s_tot;
    int lane = tid & 31, w = tid >> 5;
    int seg = 0, incl = 0;
    int BPT = nbins >> 8;
    if (tid < 256) {
        int base = tid * BPT;
        for (int i = 0; i < BPT; i++) seg += (int)h[base + i];
        incl = seg;
        #pragma unroll
        for (int off = 1; off < 32; off <<= 1) {
            int u = __shfl_down_sync(0xffffffffu, incl, off);
            if (lane + off < 32) incl += u;
        }
        if (lane == 0) wsuf[w] = incl;   // warp totals (temporarily)
    }
    __syncthreads();
    if (tid < 32) {
        int t = (tid < 8) ? wsuf[tid] : 0;
        int inc = t;
        #pragma unroll
        for (int off = 1; off < 8; off <<= 1) {
            int u = __shfl_down_sync(0xffffffffu, inc, off);
            if (tid + off < 8) inc += u;
        }
        if (tid < 8) wsuf[tid] = inc - t;   // suffix-exclusive across warps
        if (tid == 0) s_tot = inc;          // grand total
    }
    __syncthreads();
    if (tid < 256) {
        int sufExcl = wsuf[w] + (incl - seg);
        int sufIncl = sufExcl + seg;
        if (sufExcl < k && sufIncl >= k) {  // exactly one owner thread
            int cum = sufExcl;
            int base = tid * BPT;
            for (int i = BPT - 1; i >= 0; i--) {
                int c = (int)h[base + i];
                if (cum + c >= k) { *out_v = base + i; *out_kr = k - cum; break; }
                cum += c;
            }
        }
        if (tid == 0 && s_tot < k) {
            *out_v = 0; *out_kr = k - (s_tot - (int)h[0]);
        }
    }
    __syncthreads();
}

// One block per (b,scale), all 192 blocks co-resident. 12-bit radix select:
//  pass A: full scan -> 4096-bin histogram of key>>20 (light path only)
//  pass B: full scan -> sum keys above the bucket; compact bucket members
//          (~3-6% of N) to g_cand; sub-histogram their bits [19:8]
//  pass C: candidates -> sum above; 256-bin histogram of final byte + values
//  Final tie handling identical to prior rounds. Last block out finalizes.
__global__ __launch_bounds__(1024) void k_select(float* __restrict__ out)
{
    int b = blockIdx.x, s = blockIdx.y;
    int N = (s == 0) ? 49152 : ((s == 1) ? 12288 : 3072);
    size_t off = (s == 0) ? 0
               : (s == 1) ? (size_t)64 * 49152
                          : (size_t)64 * (49152 + 12288);
    const unsigned* __restrict__ keys = g_negkey + off + (size_t)b * N;
    unsigned* __restrict__ cand = g_cand + off + (size_t)b * N;

    int np = g_numpos[s * 64 + b];
    int k = 3 * (np > 1 ? np : 1);

    __shared__ unsigned hist[NBIN];
    __shared__ float fsb[256];
    __shared__ int s_v, s_kr, snc;
    __shared__ float red[32];

    int tid = threadIdx.x;
    int lane = tid & 31;
    int n4 = N >> 2;
    const uint4* k4 = (const uint4*)keys;

    for (int z = tid; z < NBIN; z += 1024) hist[z] = 0;
    if (tid == 0) snc = 0;
    __syncthreads();

    // pass A: 12-bit histogram (warp-aggregated to tame popular exp bins)
    for (int idx = tid; idx < n4; idx += 1024) {
        uint4 q = __ldg(k4 + idx);
        unsigned kk[4] = {q.x, q.y, q.z, q.w};
        #pragma unroll
        for (int e = 0; e < 4; e++) {
            unsigned bkt = kk[e] >> 20;
            unsigned am = __activemask();
            unsigned mm = __match_any_sync(am, bkt);
            if (lane == __ffs(mm) - 1)
                atomicAdd(&hist[bkt], (unsigned)__popc(mm));
        }
    }
    __syncthreads();
    selectHi(hist, NBIN, k, &s_v, &s_kr, tid);
    int v3 = s_v;
    int kr = s_kr;
    __syncthreads();
    for (int z = tid; z < NBIN; z += 1024) hist[z] = 0;
    __syncthreads();

    float lsum = 0.f;

    // pass B: sum above-bucket, compact bucket members + sub-histogram
    for (int idx = tid; idx < n4; idx += 1024) {
        uint4 q = __ldg(k4 + idx);
        unsigned kk[4] = {q.x, q.y, q.z, q.w};
        #pragma unroll
        for (int e = 0; e < 4; e++) {
            unsigned key = kk[e];
            int bin = (int)(key >> 20);
            if (bin > v3) lsum += __uint_as_float(key & 0x7fffffffu);
            else if (bin == v3) {
                unsigned am = __activemask();
                int leader = __ffs(am) - 1;
                int base;
                if (lane == leader) base = atomicAdd(&snc, __popc(am));
                base = __shfl_sync(am, base, leader);
                base += __popc(am & ((1u << lane) - 1u));
                cand[base] = key;
                atomicAdd(&hist[(key >> 8) & 4095u], 1u);
            }
        }
    }
    __syncthreads();
    selectHi(hist, NBIN, kr, &s_v, &s_kr, tid);
    int v2 = s_v;
    int kr2 = s_kr;
    int nc = snc;
    __syncthreads();
    if (tid < 256) { hist[tid] = 0; fsb[tid] = 0.f; }
    __syncthreads();

    // pass C: candidates only
    for (int z = tid; z < nc; z += 1024) {
        unsigned key = cand[z];
        int mid = (int)((key >> 8) & 4095u);
        if (mid > v2) lsum += __uint_as_float(key & 0x7fffffffu);
        else if (mid == v2) {
            unsigned bkt = key & 255u;
            atomicAdd(&hist[bkt], 1u);
            atomicAdd(&fsb[bkt], __uint_as_float(key & 0x7fffffffu));
        }
    }
    __syncthreads();
    selectHi(hist, 256, kr2, &s_v, &s_kr, tid);
    int v0 = s_v;
    int krF = s_kr;
    unsigned T = ((unsigned)v3 << 20) | ((unsigned)v2 << 8) | (unsigned)v0;

    if (tid < 256 && tid > v0) lsum += fsb[tid];

    #pragma unroll
    for (int o = 16; o; o >>= 1) lsum += __shfl_down_sync(0xffffffffu, lsum, o);
    if (lane == 0) red[tid >> 5] = lsum;
    __syncthreads();
    if (tid < 32) {
        float v = red[tid];
        #pragma unroll
        for (int o = 16; o; o >>= 1) v += __shfl_down_sync(0xffffffffu, v, o);
        if (tid == 0) {
            if (T & 0x80000000u)   // real threshold -> ties contribute
                v += (float)krF * __uint_as_float(T & 0x7fffffffu);
            if (v != 0.f) atomicAdd(&g_total, v);

            // last-block-out finalizer
            __threadfence();
            unsigned done = atomicAdd(&g_done, 1u);
            if (done == 191u) {
                float tot = atomicAdd(&g_total, 0.0f);  // ordered read
                out[0] = tot * (1.0f / 64.0f);
                g_total = 0.0f;
                for (int z = 0; z < 192; z++) g_numpos[z] = 0;
                g_done = 0u;
            }
        }
    }
}

extern "C" void kernel_launch(void* const* d_in, const int* in_sizes, int n_in,
                              void* d_out, int out_size)
{
    const float *pred0 = 0, *pred1 = 0, *pred2 = 0, *gtb = 0;
    const int *gtl = 0;
    for (int i = 0; i < n_in; ++i) {
        switch (in_sizes[i]) {
            case 25165824: pred0 = (const float*)d_in[i]; break; // 64*24*128*128
            case 6291456:  pred1 = (const float*)d_in[i]; break; // 64*24*64*64
            case 1572864:  pred2 = (const float*)d_in[i]; break; // 64*24*32*32
            case 8192:     gtb   = (const float*)d_in[i]; break; // 64*32*4
            case 2048:     gtl   = (const int*)d_in[i];   break; // 64*32
        }
    }

    k_all<<<dim3(84, 64), 256>>>(pred0, pred1, pred2, gtb, gtl);
    k_select<<<dim3(64, 3), 1024>>>((float*)d_out);
}